// round 3
// baseline (speedup 1.0000x reference)
#include <cuda_runtime.h>
#include <math.h>

#define Nn  50000
#define Ee  300000
#define NCc 12500
#define ECc 75000

// output layout: v_c [NC*128] | e_c [EC*128] | v_skip [N*128] | e_skip [E*128]
#define OFF_EC 1600000
#define OFF_V  11200000
#define OFF_E  17600000

// ---------------- device scratch (no allocations allowed) ----------------
__device__ float g_agg[Nn * 128];     // segment-sum of updated edge features
__device__ float g_deg[Nn];           // per-node incident (dst) edge count
__device__ float g_cposs[NCc * 2];    // cluster position sums
__device__ float g_ccnt[NCc];         // cluster counts
__device__ float g_cpos[NCc * 2];     // coarse positions (mean)
__device__ float g_cinv[NCc];         // 1 / max(count,1)

__device__ __forceinline__ float selu_f(float x) {
    // jax.nn.selu: scale * where(x>0, x, alpha*expm1(x))
    return x > 0.f ? 1.0507009873554805f * x : 1.7580993408473766f * expm1f(x);
}

// 16-step K inner product: acc[8][8] += A(64 rows, STRIDE floats/row)[:,0:16] @ Bs(16x128)
template <int STRIDE>
__device__ __forceinline__ void mma_tile16(const float* A, const float* Bs,
                                           int r0, int c0, float (&acc)[8][8]) {
#pragma unroll
    for (int k = 0; k < 16; k++) {
        float a[8];
#pragma unroll
        for (int i = 0; i < 8; i++) a[i] = A[(r0 + i) * STRIDE + k];
        float4 bA = *(const float4*)&Bs[k * 128 + c0];
        float4 bB = *(const float4*)&Bs[k * 128 + c0 + 4];
#pragma unroll
        for (int i = 0; i < 8; i++) {
            float av = a[i];
            acc[i][0] = fmaf(av, bA.x, acc[i][0]);
            acc[i][1] = fmaf(av, bA.y, acc[i][1]);
            acc[i][2] = fmaf(av, bA.z, acc[i][2]);
            acc[i][3] = fmaf(av, bA.w, acc[i][3]);
            acc[i][4] = fmaf(av, bB.x, acc[i][4]);
            acc[i][5] = fmaf(av, bB.y, acc[i][5]);
            acc[i][6] = fmaf(av, bB.z, acc[i][6]);
            acc[i][7] = fmaf(av, bB.w, acc[i][7]);
        }
    }
}

// Hidden layer: acc += Hs(64x128, row stride 129) @ Wm(128x128), Wm streamed via Bs
__device__ __forceinline__ void layer_from_Hs(const float* __restrict__ Wm,
                                              const float* Hs, float* Bs,
                                              int r0, int c0, int t, float (&acc)[8][8]) {
    for (int kt = 0; kt < 128; kt += 16) {
        __syncthreads();  // previous Bs consumers / prior Hs writers done
        const float4* wsrc = (const float4*)(Wm + kt * 128);
        float4* bdst = (float4*)Bs;
#pragma unroll
        for (int i = 0; i < 4; i++) bdst[i * 128 + t] = wsrc[i * 128 + t];
        __syncthreads();
        mma_tile16<129>(Hs + kt, Bs, r0, c0, acc);
    }
    __syncthreads();  // all Hs reads done before caller overwrites Hs
}

// ---------------- edge update: e += MLP([e, v[src], v[dst]]); agg[dst] += e ----------------
__global__ void __launch_bounds__(128) edge_kernel(
    float* __restrict__ e, const float* __restrict__ v,
    const int* __restrict__ src, const int* __restrict__ dst,
    const float* __restrict__ w0, const float* __restrict__ b0,
    const float* __restrict__ w1, const float* __restrict__ b1,
    const float* __restrict__ w2, const float* __restrict__ b2,
    float* __restrict__ agg) {
    __shared__ alignas(16) float As[64 * 17];
    __shared__ alignas(16) float Bs[16 * 128];
    __shared__ alignas(16) float Hs[64 * 129];
    __shared__ int s_src[64], s_dst[64];

    const int t = threadIdx.x;
    const int row0 = blockIdx.x * 64;
    if (t < 64) {
        int r = row0 + t;
        if (r >= Ee) r = Ee - 1;
        s_src[t] = src[r];
        s_dst[t] = dst[r];
    }
    const int c0 = (t & 15) * 8;
    const int r0 = (t >> 4) * 8;
    float acc[8][8];
#pragma unroll
    for (int i = 0; i < 8; i++)
#pragma unroll
        for (int j = 0; j < 8; j++) acc[i][j] = 0.f;

    // layer 0: K = 384 (concat [e | v[src] | v[dst]])
    for (int kt = 0; kt < 384; kt += 16) {
        __syncthreads();
#pragma unroll
        for (int i = 0; i < 2; i++) {
            int f = t * 2 + i;
            int ar = f >> 2;
            int kl = (f & 3) << 2;
            int k = kt + kl;
            int grow = row0 + ar;
            if (grow >= Ee) grow = Ee - 1;
            float4 val;
            if (k < 128)       val = *(const float4*)(e + (size_t)grow * 128 + k);
            else if (k < 256)  val = *(const float4*)(v + (size_t)s_src[ar] * 128 + (k - 128));
            else               val = *(const float4*)(v + (size_t)s_dst[ar] * 128 + (k - 256));
            float* q = &As[ar * 17 + kl];
            q[0] = val.x; q[1] = val.y; q[2] = val.z; q[3] = val.w;
        }
        const float4* wsrc = (const float4*)(w0 + (size_t)kt * 128);
#pragma unroll
        for (int i = 0; i < 4; i++) ((float4*)Bs)[i * 128 + t] = wsrc[i * 128 + t];
        __syncthreads();
        mma_tile16<17>(As, Bs, r0, c0, acc);
    }
#pragma unroll
    for (int i = 0; i < 8; i++)
#pragma unroll
        for (int j = 0; j < 8; j++) {
            Hs[(r0 + i) * 129 + c0 + j] = selu_f(acc[i][j] + __ldg(&b0[c0 + j]));
            acc[i][j] = 0.f;
        }

    layer_from_Hs(w1, Hs, Bs, r0, c0, t, acc);
#pragma unroll
    for (int i = 0; i < 8; i++)
#pragma unroll
        for (int j = 0; j < 8; j++) {
            Hs[(r0 + i) * 129 + c0 + j] = selu_f(acc[i][j] + __ldg(&b1[c0 + j]));
            acc[i][j] = 0.f;
        }

    layer_from_Hs(w2, Hs, Bs, r0, c0, t, acc);

    // epilogue: residual add + in-place e store + segment-sum atomics
#pragma unroll
    for (int i = 0; i < 8; i++) {
        int row = row0 + r0 + i;
        if (row < Ee) {
            int dn = s_dst[r0 + i];
            float* erow = e + (size_t)row * 128 + c0;
            float* arow = agg + (size_t)dn * 128 + c0;
#pragma unroll
            for (int j = 0; j < 8; j++) {
                float res = erow[j] + acc[i][j] + __ldg(&b2[c0 + j]);
                erow[j] = res;
                atomicAdd(&arow[j], res);
            }
        }
    }
}

// ---------------- node update: v += MLP([v, agg/deg]) ----------------
__global__ void __launch_bounds__(128) node_kernel(
    float* __restrict__ v, const float* __restrict__ agg, const float* __restrict__ deg,
    const float* __restrict__ w0, const float* __restrict__ b0,
    const float* __restrict__ w1, const float* __restrict__ b1,
    const float* __restrict__ w2, const float* __restrict__ b2) {
    __shared__ alignas(16) float As[64 * 17];
    __shared__ alignas(16) float Bs[16 * 128];
    __shared__ alignas(16) float Hs[64 * 129];
    __shared__ float s_inv[64];

    const int t = threadIdx.x;
    const int row0 = blockIdx.x * 64;
    if (t < 64) {
        int r = row0 + t;
        if (r >= Nn) r = Nn - 1;
        s_inv[t] = 1.f / fmaxf(deg[r], 1.f);
    }
    const int c0 = (t & 15) * 8;
    const int r0 = (t >> 4) * 8;
    float acc[8][8];
#pragma unroll
    for (int i = 0; i < 8; i++)
#pragma unroll
        for (int j = 0; j < 8; j++) acc[i][j] = 0.f;

    // layer 0: K = 256 (concat [v | agg/deg])
    for (int kt = 0; kt < 256; kt += 16) {
        __syncthreads();
#pragma unroll
        for (int i = 0; i < 2; i++) {
            int f = t * 2 + i;
            int ar = f >> 2;
            int kl = (f & 3) << 2;
            int k = kt + kl;
            int grow = row0 + ar;
            if (grow >= Nn) grow = Nn - 1;
            float4 val;
            if (k < 128) {
                val = *(const float4*)(v + (size_t)grow * 128 + k);
            } else {
                val = *(const float4*)(agg + (size_t)grow * 128 + (k - 128));
                float sc = s_inv[ar];
                val.x *= sc; val.y *= sc; val.z *= sc; val.w *= sc;
            }
            float* q = &As[ar * 17 + kl];
            q[0] = val.x; q[1] = val.y; q[2] = val.z; q[3] = val.w;
        }
        const float4* wsrc = (const float4*)(w0 + (size_t)kt * 128);
#pragma unroll
        for (int i = 0; i < 4; i++) ((float4*)Bs)[i * 128 + t] = wsrc[i * 128 + t];
        __syncthreads();
        mma_tile16<17>(As, Bs, r0, c0, acc);
    }
#pragma unroll
    for (int i = 0; i < 8; i++)
#pragma unroll
        for (int j = 0; j < 8; j++) {
            Hs[(r0 + i) * 129 + c0 + j] = selu_f(acc[i][j] + __ldg(&b0[c0 + j]));
            acc[i][j] = 0.f;
        }
    layer_from_Hs(w1, Hs, Bs, r0, c0, t, acc);
#pragma unroll
    for (int i = 0; i < 8; i++)
#pragma unroll
        for (int j = 0; j < 8; j++) {
            Hs[(r0 + i) * 129 + c0 + j] = selu_f(acc[i][j] + __ldg(&b1[c0 + j]));
            acc[i][j] = 0.f;
        }
    layer_from_Hs(w2, Hs, Bs, r0, c0, t, acc);

#pragma unroll
    for (int i = 0; i < 8; i++) {
        int row = row0 + r0 + i;
        if (row < Nn) {
            float* vrow = v + (size_t)row * 128 + c0;
#pragma unroll
            for (int j = 0; j < 8; j++) vrow[j] = vrow[j] + acc[i][j] + __ldg(&b2[c0 + j]);
        }
    }
}

// ---------------- pooling msg: MLP([v, rel_feat]) -> atomic into v_c sums ----------------
__global__ void __launch_bounds__(128) pool_kernel(
    const float* __restrict__ v, const float* __restrict__ pos,
    const int* __restrict__ cluster, const float* __restrict__ cpos,
    const float* __restrict__ w0, const float* __restrict__ b0,
    const float* __restrict__ w1, const float* __restrict__ b1,
    const float* __restrict__ w2, const float* __restrict__ b2,
    float* __restrict__ vc) {
    __shared__ alignas(16) float As[64 * 17];
    __shared__ alignas(16) float Bs[16 * 128];
    __shared__ alignas(16) float Hs[64 * 129];
    __shared__ float s_rel[64];
    __shared__ int s_cl[64];

    const int t = threadIdx.x;
    const int row0 = blockIdx.x * 64;
    if (t < 64) {
        int r = row0 + t;
        if (r >= Nn) r = Nn - 1;
        int cl = cluster[r];
        float dx = pos[2 * r] - cpos[2 * cl];
        float dy = pos[2 * r + 1] - cpos[2 * cl + 1];
        s_rel[t] = sqrtf(dx * dx + dy * dy + 1e-12f);
        s_cl[t] = cl;
    }
    const int c0 = (t & 15) * 8;
    const int r0 = (t >> 4) * 8;
    float acc[8][8];
#pragma unroll
    for (int i = 0; i < 8; i++)
#pragma unroll
        for (int j = 0; j < 8; j++) acc[i][j] = 0.f;

    // layer 0: first 128 input dims from v
    for (int kt = 0; kt < 128; kt += 16) {
        __syncthreads();
#pragma unroll
        for (int i = 0; i < 2; i++) {
            int f = t * 2 + i;
            int ar = f >> 2;
            int kl = (f & 3) << 2;
            int grow = row0 + ar;
            if (grow >= Nn) grow = Nn - 1;
            float4 val = *(const float4*)(v + (size_t)grow * 128 + kt + kl);
            float* q = &As[ar * 17 + kl];
            q[0] = val.x; q[1] = val.y; q[2] = val.z; q[3] = val.w;
        }
        const float4* wsrc = (const float4*)(w0 + (size_t)kt * 128);
#pragma unroll
        for (int i = 0; i < 4; i++) ((float4*)Bs)[i * 128 + t] = wsrc[i * 128 + t];
        __syncthreads();
        mma_tile16<17>(As, Bs, r0, c0, acc);
    }
    // input dim 128: rel_feat scalar * w0 row 128
#pragma unroll
    for (int i = 0; i < 8; i++) {
        float rl = s_rel[r0 + i];
#pragma unroll
        for (int j = 0; j < 8; j++)
            acc[i][j] = fmaf(rl, __ldg(&w0[128 * 128 + c0 + j]), acc[i][j]);
    }
#pragma unroll
    for (int i = 0; i < 8; i++)
#pragma unroll
        for (int j = 0; j < 8; j++) {
            Hs[(r0 + i) * 129 + c0 + j] = selu_f(acc[i][j] + __ldg(&b0[c0 + j]));
            acc[i][j] = 0.f;
        }
    layer_from_Hs(w1, Hs, Bs, r0, c0, t, acc);
#pragma unroll
    for (int i = 0; i < 8; i++)
#pragma unroll
        for (int j = 0; j < 8; j++) {
            Hs[(r0 + i) * 129 + c0 + j] = selu_f(acc[i][j] + __ldg(&b1[c0 + j]));
            acc[i][j] = 0.f;
        }
    layer_from_Hs(w2, Hs, Bs, r0, c0, t, acc);

#pragma unroll
    for (int i = 0; i < 8; i++) {
        int row = row0 + r0 + i;
        if (row < Nn) {
            int cl = s_cl[r0 + i];
            float* crow = vc + (size_t)cl * 128 + c0;
#pragma unroll
            for (int j = 0; j < 8; j++)
                atomicAdd(&crow[j], acc[i][j] + __ldg(&b2[c0 + j]));
        }
    }
}

// ---------------- coarse edge encoder: MLP(crel_feat scalar) ----------------
__global__ void __launch_bounds__(128) eenc_kernel(
    const int* __restrict__ cei, const float* __restrict__ cpos,
    const float* __restrict__ w0, const float* __restrict__ b0,
    const float* __restrict__ w1, const float* __restrict__ b1,
    const float* __restrict__ w2, const float* __restrict__ b2,
    float* __restrict__ ec) {
    __shared__ alignas(16) float Bs[16 * 128];
    __shared__ alignas(16) float Hs[64 * 129];
    __shared__ float s_crel[64];

    const int t = threadIdx.x;
    const int row0 = blockIdx.x * 64;
    if (t < 64) {
        int r = row0 + t;
        if (r >= ECc) r = ECc - 1;
        int a = cei[r];
        int b = cei[ECc + r];
        float dx = cpos[2 * a] - cpos[2 * b];
        float dy = cpos[2 * a + 1] - cpos[2 * b + 1];
        s_crel[t] = sqrtf(dx * dx + dy * dy + 1e-12f);
    }
    const int c0 = (t & 15) * 8;
    const int r0 = (t >> 4) * 8;
    __syncthreads();

    // layer 0: K = 1
#pragma unroll
    for (int i = 0; i < 8; i++) {
        float cr = s_crel[r0 + i];
#pragma unroll
        for (int j = 0; j < 8; j++)
            Hs[(r0 + i) * 129 + c0 + j] =
                selu_f(fmaf(cr, __ldg(&w0[c0 + j]), __ldg(&b0[c0 + j])));
    }
    float acc[8][8];
#pragma unroll
    for (int i = 0; i < 8; i++)
#pragma unroll
        for (int j = 0; j < 8; j++) acc[i][j] = 0.f;

    layer_from_Hs(w1, Hs, Bs, r0, c0, t, acc);
#pragma unroll
    for (int i = 0; i < 8; i++)
#pragma unroll
        for (int j = 0; j < 8; j++) {
            Hs[(r0 + i) * 129 + c0 + j] = selu_f(acc[i][j] + __ldg(&b1[c0 + j]));
            acc[i][j] = 0.f;
        }
    layer_from_Hs(w2, Hs, Bs, r0, c0, t, acc);

#pragma unroll
    for (int i = 0; i < 8; i++) {
        int row = row0 + r0 + i;
        if (row < ECc) {
            float* erow = ec + (size_t)row * 128 + c0;
#pragma unroll
            for (int j = 0; j < 8; j++) erow[j] = acc[i][j] + __ldg(&b2[c0 + j]);
        }
    }
}

// ---------------- small helpers ----------------
__global__ void deg_scatter(const int* __restrict__ dst, float* __restrict__ deg) {
    int i = blockIdx.x * blockDim.x + threadIdx.x;
    if (i < Ee) atomicAdd(&deg[dst[i]], 1.f);
}
__global__ void cpos_scatter(const float* __restrict__ pos, const int* __restrict__ cluster,
                             float* __restrict__ cposs, float* __restrict__ ccnt) {
    int i = blockIdx.x * blockDim.x + threadIdx.x;
    if (i < Nn) {
        int c = cluster[i];
        atomicAdd(&cposs[2 * c], pos[2 * i]);
        atomicAdd(&cposs[2 * c + 1], pos[2 * i + 1]);
        atomicAdd(&ccnt[c], 1.f);
    }
}
__global__ void cpos_fin(const float* __restrict__ cposs, const float* __restrict__ ccnt,
                         float* __restrict__ cpos, float* __restrict__ cinv) {
    int c = blockIdx.x * blockDim.x + threadIdx.x;
    if (c < NCc) {
        float inv = 1.f / fmaxf(ccnt[c], 1.f);
        cpos[2 * c] = cposs[2 * c] * inv;
        cpos[2 * c + 1] = cposs[2 * c + 1] * inv;
        cinv[c] = inv;
    }
}
__global__ void vc_scale(float* __restrict__ vc, const float* __restrict__ cinv) {
    int i = blockIdx.x * blockDim.x + threadIdx.x;
    if (i < NCc * 128) vc[i] *= cinv[i >> 7];
}

// ---------------- launch ----------------
extern "C" void kernel_launch(void* const* d_in, const int* in_sizes, int n_in,
                              void* d_out, int out_size) {
    const float* v0      = (const float*)d_in[0];
    const float* e0      = (const float*)d_in[1];
    const float* pos     = (const float*)d_in[2];
    const int*   ei      = (const int*)d_in[3];
    const int*   cluster = (const int*)d_in[4];
    const int*   cei     = (const int*)d_in[5];
    const float* ew0 = (const float*)d_in[6],  *eb0 = (const float*)d_in[7];
    const float* ew1 = (const float*)d_in[8],  *eb1 = (const float*)d_in[9];
    const float* ew2 = (const float*)d_in[10], *eb2 = (const float*)d_in[11];
    const float* nw0 = (const float*)d_in[12], *nb0 = (const float*)d_in[13];
    const float* nw1 = (const float*)d_in[14], *nb1 = (const float*)d_in[15];
    const float* nw2 = (const float*)d_in[16], *nb2 = (const float*)d_in[17];
    const float* pw0 = (const float*)d_in[18], *pb0 = (const float*)d_in[19];
    const float* pw1 = (const float*)d_in[20], *pb1 = (const float*)d_in[21];
    const float* pw2 = (const float*)d_in[22], *pb2 = (const float*)d_in[23];
    const float* qw0 = (const float*)d_in[24], *qb0 = (const float*)d_in[25];
    const float* qw1 = (const float*)d_in[26], *qb1 = (const float*)d_in[27];
    const float* qw2 = (const float*)d_in[28], *qb2 = (const float*)d_in[29];

    float* out    = (float*)d_out;
    float* out_vc = out;             // [NC,128]
    float* out_ec = out + OFF_EC;    // [EC,128]
    float* vbuf   = out + OFF_V;     // v lives here (becomes v_skip)
    float* ebuf   = out + OFF_E;     // e lives here (becomes e_skip)

    float *agg, *deg, *cposs, *ccnt, *cpos, *cinv;
    cudaGetSymbolAddress((void**)&agg,   g_agg);
    cudaGetSymbolAddress((void**)&deg,   g_deg);
    cudaGetSymbolAddress((void**)&cposs, g_cposs);
    cudaGetSymbolAddress((void**)&ccnt,  g_ccnt);
    cudaGetSymbolAddress((void**)&cpos,  g_cpos);
    cudaGetSymbolAddress((void**)&cinv,  g_cinv);

    cudaMemcpyAsync(vbuf, v0, sizeof(float) * (size_t)Nn * 128, cudaMemcpyDeviceToDevice, 0);
    cudaMemcpyAsync(ebuf, e0, sizeof(float) * (size_t)Ee * 128, cudaMemcpyDeviceToDevice, 0);

    const int* src  = ei;
    const int* dstp = ei + Ee;

    cudaMemsetAsync(deg, 0, sizeof(float) * Nn, 0);
    deg_scatter<<<(Ee + 255) / 256, 256>>>(dstp, deg);

    for (int d = 0; d < 4; d++) {
        cudaMemsetAsync(agg, 0, sizeof(float) * (size_t)Nn * 128, 0);
        edge_kernel<<<(Ee + 63) / 64, 128>>>(
            ebuf, vbuf, src, dstp,
            ew0 + (size_t)d * 384 * 128, eb0 + d * 128,
            ew1 + (size_t)d * 128 * 128, eb1 + d * 128,
            ew2 + (size_t)d * 128 * 128, eb2 + d * 128, agg);
        node_kernel<<<(Nn + 63) / 64, 128>>>(
            vbuf, agg, deg,
            nw0 + (size_t)d * 256 * 128, nb0 + d * 128,
            nw1 + (size_t)d * 128 * 128, nb1 + d * 128,
            nw2 + (size_t)d * 128 * 128, nb2 + d * 128);
    }

    cudaMemsetAsync(cposs, 0, sizeof(float) * NCc * 2, 0);
    cudaMemsetAsync(ccnt, 0, sizeof(float) * NCc, 0);
    cpos_scatter<<<(Nn + 255) / 256, 256>>>(pos, cluster, cposs, ccnt);
    cpos_fin<<<(NCc + 255) / 256, 256>>>(cposs, ccnt, cpos, cinv);

    cudaMemsetAsync(out_vc, 0, sizeof(float) * NCc * 128, 0);
    pool_kernel<<<(Nn + 63) / 64, 128>>>(vbuf, pos, cluster, cpos,
                                         pw0, pb0, pw1, pb1, pw2, pb2, out_vc);
    vc_scale<<<(NCc * 128 + 255) / 256, 256>>>(out_vc, cinv);

    eenc_kernel<<<(ECc + 63) / 64, 128>>>(cei, cpos, qw0, qb0, qw1, qb1, qw2, qb2, out_ec);
}

// round 4
// speedup vs baseline: 1.1413x; 1.1413x over previous
#include <cuda_runtime.h>
#include <math.h>

#define Nn  50000
#define Ee  300000
#define NCc 12500
#define ECc 75000

#define OFF_EC 1600000
#define OFF_V  11200000
#define OFF_E  17600000

typedef unsigned long long ull;

// smem layout (floats): Ad[64*36]=2304 | Bs[16*160]=2560 | Hs[64*132]=8448 | idx area
#define AD_OFF 0
#define BS_OFF 2304
#define HS_OFF 4864
#define IX_OFF 13312
#define SMEM_BYTES ((13312 + 128) * 4)

// ---------------- device scratch ----------------
__device__ float g_agg[Nn * 128];
__device__ float g_deg[Nn];
__device__ float g_cposs[NCc * 2];
__device__ float g_ccnt[NCc];
__device__ float g_cpos[NCc * 2];
__device__ float g_cinv[NCc];

__device__ __forceinline__ float selu_f(float x) {
    return x > 0.f ? 1.0507009873554805f * x : 1.7580993408473766f * expm1f(x);
}
__device__ __forceinline__ void ffma2(ull& d, ull a, ull b) {
    asm("fma.rn.f32x2 %0, %1, %2, %0;" : "+l"(d) : "l"(a), "l"(b));
}
__device__ __forceinline__ float2 unpk(ull p) {
    float2 f;
    asm("mov.b64 {%0, %1}, %2;" : "=f"(f.x), "=f"(f.y) : "l"(p));
    return f;
}
__device__ __forceinline__ ull dupf(float x) {
    ull r;
    asm("mov.b64 %0, {%1, %1};" : "=l"(r) : "f"(x));
    return r;
}

__device__ __forceinline__ void acc_init(ull (&acc)[8][4], const float* __restrict__ b, int c0) {
    ull bb[4];
#pragma unroll
    for (int j = 0; j < 4; j++) bb[j] = *(const ull*)&b[c0 + 2 * j];
#pragma unroll
    for (int i = 0; i < 8; i++)
#pragma unroll
        for (int j = 0; j < 4; j++) acc[i][j] = bb[j];
}

// Bs layout: Bs[k*160 + (c/8)*10 + (c%8)]  (group bases 10g mod 32 = all even residues)
__device__ __forceinline__ void fill_Bs(float* Bs, const float* __restrict__ W, int kt, int t) {
    const float4* wsrc = (const float4*)(W + (size_t)kt * 128);
#pragma unroll
    for (int i = 0; i < 4; i++) {
        int fi = i * 128 + t;          // 0..511 float4s of the 16x128 tile
        float4 w = wsrc[fi];
        int k = fi >> 5;               // k row (32 float4 per row)
        int q = fi & 31;
        int g = q >> 1;                // column group 0..15
        int m = (q & 1) * 4;           // 0 or 4 within group
        float* d = &Bs[k * 160 + g * 10 + m];
        *(float2*)(d)     = make_float2(w.x, w.y);
        *(float2*)(d + 2) = make_float2(w.z, w.w);
    }
}

// duplicated-pair A tile: Ad[row*36 + 2k] = Ad[row*36 + 2k + 1] = a(row,k)
__device__ __forceinline__ void fill_Ad_from_Hs(float* Ad, const float* Hs, int kt, int t) {
#pragma unroll
    for (int i = 0; i < 2; i++) {
        int f = t * 2 + i;             // 0..255
        int ar = f >> 2;               // row 0..63
        int kl = (f & 3) << 2;         // 0,4,8,12
        float4 v4 = *(const float4*)&Hs[ar * 132 + kt + kl];
        float* q = &Ad[ar * 36 + 2 * kl];
        *(float4*)(q)     = make_float4(v4.x, v4.x, v4.y, v4.y);
        *(float4*)(q + 4) = make_float4(v4.z, v4.z, v4.w, v4.w);
    }
}

__device__ __forceinline__ void mma16(const float* Ad, const float* Bs,
                                      int r0, int c0, ull (&acc)[8][4]) {
    const int gb = (c0 >> 3) * 10;
#pragma unroll
    for (int k2 = 0; k2 < 8; k2++) {
        ulonglong2 a[8];
#pragma unroll
        for (int i = 0; i < 8; i++)
            a[i] = *(const ulonglong2*)&Ad[(r0 + i) * 36 + 4 * k2];
        {
            const float* bp = &Bs[(2 * k2) * 160 + gb];
            ull b0 = *(const ull*)(bp + 0), b1 = *(const ull*)(bp + 2);
            ull b2 = *(const ull*)(bp + 4), b3 = *(const ull*)(bp + 6);
#pragma unroll
            for (int i = 0; i < 8; i++) {
                ffma2(acc[i][0], a[i].x, b0);
                ffma2(acc[i][1], a[i].x, b1);
                ffma2(acc[i][2], a[i].x, b2);
                ffma2(acc[i][3], a[i].x, b3);
            }
        }
        {
            const float* bp = &Bs[(2 * k2 + 1) * 160 + gb];
            ull b0 = *(const ull*)(bp + 0), b1 = *(const ull*)(bp + 2);
            ull b2 = *(const ull*)(bp + 4), b3 = *(const ull*)(bp + 6);
#pragma unroll
            for (int i = 0; i < 8; i++) {
                ffma2(acc[i][0], a[i].y, b0);
                ffma2(acc[i][1], a[i].y, b1);
                ffma2(acc[i][2], a[i].y, b2);
                ffma2(acc[i][3], a[i].y, b3);
            }
        }
    }
}

__device__ __forceinline__ void selu_store(float* Hs, ull (&acc)[8][4], int r0, int c0) {
#pragma unroll
    for (int i = 0; i < 8; i++) {
        float2 p0 = unpk(acc[i][0]), p1 = unpk(acc[i][1]);
        float2 p2 = unpk(acc[i][2]), p3 = unpk(acc[i][3]);
        *(float4*)&Hs[(r0 + i) * 132 + c0] =
            make_float4(selu_f(p0.x), selu_f(p0.y), selu_f(p1.x), selu_f(p1.y));
        *(float4*)&Hs[(r0 + i) * 132 + c0 + 4] =
            make_float4(selu_f(p2.x), selu_f(p2.y), selu_f(p3.x), selu_f(p3.y));
    }
}

// hidden 128->128 layer: acc += selu-activated Hs @ W
__device__ __forceinline__ void hidden_layer(const float* __restrict__ W,
                                             const float* Hs, float* Ad, float* Bs,
                                             int t, int r0, int c0, ull (&acc)[8][4]) {
    for (int kt = 0; kt < 128; kt += 16) {
        __syncthreads();
        fill_Ad_from_Hs(Ad, Hs, kt, t);
        fill_Bs(Bs, W, kt, t);
        __syncthreads();
        mma16(Ad, Bs, r0, c0, acc);
    }
    __syncthreads();  // Hs/Ad consumers done before caller rewrites Hs
}

// ---------------- edge: e += MLP([e, v[src], v[dst]]); agg[dst] += e ----------------
__global__ void __launch_bounds__(128) edge_kernel(
    float* __restrict__ e, const float* __restrict__ v,
    const int* __restrict__ src, const int* __restrict__ dst,
    const float* __restrict__ w0, const float* __restrict__ b0,
    const float* __restrict__ w1, const float* __restrict__ b1,
    const float* __restrict__ w2, const float* __restrict__ b2,
    float* __restrict__ agg) {
    extern __shared__ float sm[];
    float* Ad = sm + AD_OFF;
    float* Bs = sm + BS_OFF;
    float* Hs = sm + HS_OFF;
    int* s_src = (int*)(sm + IX_OFF);
    int* s_dst = s_src + 64;

    const int t = threadIdx.x;
    const int row0 = blockIdx.x * 64;
    if (t < 64) {
        int r = row0 + t;
        if (r >= Ee) r = Ee - 1;
        s_src[t] = src[r];
        s_dst[t] = dst[r];
    }
    const int c0 = (t & 15) * 8;
    const int r0 = (t >> 4) * 8;

    ull acc[8][4];
    acc_init(acc, b0, c0);

    for (int kt = 0; kt < 384; kt += 16) {
        __syncthreads();
#pragma unroll
        for (int i = 0; i < 2; i++) {
            int f = t * 2 + i;
            int ar = f >> 2;
            int kl = (f & 3) << 2;
            int k = kt + kl;
            int grow = row0 + ar;
            if (grow >= Ee) grow = Ee - 1;
            float4 val;
            if (k < 128)      val = *(const float4*)(e + (size_t)grow * 128 + k);
            else if (k < 256) val = *(const float4*)(v + (size_t)s_src[ar] * 128 + (k - 128));
            else              val = *(const float4*)(v + (size_t)s_dst[ar] * 128 + (k - 256));
            float* q = &Ad[ar * 36 + 2 * kl];
            *(float4*)(q)     = make_float4(val.x, val.x, val.y, val.y);
            *(float4*)(q + 4) = make_float4(val.z, val.z, val.w, val.w);
        }
        fill_Bs(Bs, w0, kt, t);
        __syncthreads();
        mma16(Ad, Bs, r0, c0, acc);
    }
    selu_store(Hs, acc, r0, c0);
    acc_init(acc, b1, c0);
    hidden_layer(w1, Hs, Ad, Bs, t, r0, c0, acc);
    selu_store(Hs, acc, r0, c0);
    acc_init(acc, b2, c0);
    hidden_layer(w2, Hs, Ad, Bs, t, r0, c0, acc);

#pragma unroll
    for (int i = 0; i < 8; i++) {
        int row = row0 + r0 + i;
        if (row < Ee) {
            int dn = s_dst[r0 + i];
            float* erow = e + (size_t)row * 128 + c0;
            float* arow = agg + (size_t)dn * 128 + c0;
            float2 p0 = unpk(acc[i][0]), p1 = unpk(acc[i][1]);
            float2 p2 = unpk(acc[i][2]), p3 = unpk(acc[i][3]);
            float4 e0 = *(float4*)erow;
            float4 e1 = *(float4*)(erow + 4);
            float rr[8] = {e0.x + p0.x, e0.y + p0.y, e0.z + p1.x, e0.w + p1.y,
                           e1.x + p2.x, e1.y + p2.y, e1.z + p3.x, e1.w + p3.y};
            *(float4*)erow       = make_float4(rr[0], rr[1], rr[2], rr[3]);
            *(float4*)(erow + 4) = make_float4(rr[4], rr[5], rr[6], rr[7]);
#pragma unroll
            for (int j = 0; j < 8; j++) atomicAdd(&arow[j], rr[j]);
        }
    }
}

// ---------------- node: v += MLP([v, agg/deg]) ----------------
__global__ void __launch_bounds__(128) node_kernel(
    float* __restrict__ v, const float* __restrict__ agg, const float* __restrict__ deg,
    const float* __restrict__ w0, const float* __restrict__ b0,
    const float* __restrict__ w1, const float* __restrict__ b1,
    const float* __restrict__ w2, const float* __restrict__ b2) {
    extern __shared__ float sm[];
    float* Ad = sm + AD_OFF;
    float* Bs = sm + BS_OFF;
    float* Hs = sm + HS_OFF;
    float* s_inv = sm + IX_OFF;

    const int t = threadIdx.x;
    const int row0 = blockIdx.x * 64;
    if (t < 64) {
        int r = row0 + t;
        if (r >= Nn) r = Nn - 1;
        s_inv[t] = 1.f / fmaxf(deg[r], 1.f);
    }
    const int c0 = (t & 15) * 8;
    const int r0 = (t >> 4) * 8;

    ull acc[8][4];
    acc_init(acc, b0, c0);

    for (int kt = 0; kt < 256; kt += 16) {
        __syncthreads();
#pragma unroll
        for (int i = 0; i < 2; i++) {
            int f = t * 2 + i;
            int ar = f >> 2;
            int kl = (f & 3) << 2;
            int k = kt + kl;
            int grow = row0 + ar;
            if (grow >= Nn) grow = Nn - 1;
            float4 val;
            if (k < 128) {
                val = *(const float4*)(v + (size_t)grow * 128 + k);
            } else {
                val = *(const float4*)(agg + (size_t)grow * 128 + (k - 128));
                float sc = s_inv[ar];
                val.x *= sc; val.y *= sc; val.z *= sc; val.w *= sc;
            }
            float* q = &Ad[ar * 36 + 2 * kl];
            *(float4*)(q)     = make_float4(val.x, val.x, val.y, val.y);
            *(float4*)(q + 4) = make_float4(val.z, val.z, val.w, val.w);
        }
        fill_Bs(Bs, w0, kt, t);
        __syncthreads();
        mma16(Ad, Bs, r0, c0, acc);
    }
    selu_store(Hs, acc, r0, c0);
    acc_init(acc, b1, c0);
    hidden_layer(w1, Hs, Ad, Bs, t, r0, c0, acc);
    selu_store(Hs, acc, r0, c0);
    acc_init(acc, b2, c0);
    hidden_layer(w2, Hs, Ad, Bs, t, r0, c0, acc);

#pragma unroll
    for (int i = 0; i < 8; i++) {
        int row = row0 + r0 + i;
        if (row < Nn) {
            float* vrow = v + (size_t)row * 128 + c0;
            float2 p0 = unpk(acc[i][0]), p1 = unpk(acc[i][1]);
            float2 p2 = unpk(acc[i][2]), p3 = unpk(acc[i][3]);
            float4 v0 = *(float4*)vrow;
            float4 v1 = *(float4*)(vrow + 4);
            *(float4*)vrow       = make_float4(v0.x + p0.x, v0.y + p0.y, v0.z + p1.x, v0.w + p1.y);
            *(float4*)(vrow + 4) = make_float4(v1.x + p2.x, v1.y + p2.y, v1.z + p3.x, v1.w + p3.y);
        }
    }
}

// ---------------- pool: atomic-add MLP([v, rel]) into vc sums ----------------
__global__ void __launch_bounds__(128) pool_kernel(
    const float* __restrict__ v, const float* __restrict__ pos,
    const int* __restrict__ cluster, const float* __restrict__ cpos,
    const float* __restrict__ w0, const float* __restrict__ b0,
    const float* __restrict__ w1, const float* __restrict__ b1,
    const float* __restrict__ w2, const float* __restrict__ b2,
    float* __restrict__ vc) {
    extern __shared__ float sm[];
    float* Ad = sm + AD_OFF;
    float* Bs = sm + BS_OFF;
    float* Hs = sm + HS_OFF;
    float* s_rel = sm + IX_OFF;
    int* s_cl = (int*)(sm + IX_OFF + 64);

    const int t = threadIdx.x;
    const int row0 = blockIdx.x * 64;
    if (t < 64) {
        int r = row0 + t;
        if (r >= Nn) r = Nn - 1;
        int cl = cluster[r];
        float dx = pos[2 * r] - cpos[2 * cl];
        float dy = pos[2 * r + 1] - cpos[2 * cl + 1];
        s_rel[t] = sqrtf(dx * dx + dy * dy + 1e-12f);
        s_cl[t] = cl;
    }
    const int c0 = (t & 15) * 8;
    const int r0 = (t >> 4) * 8;

    ull acc[8][4];
    acc_init(acc, b0, c0);

    for (int kt = 0; kt < 128; kt += 16) {
        __syncthreads();
#pragma unroll
        for (int i = 0; i < 2; i++) {
            int f = t * 2 + i;
            int ar = f >> 2;
            int kl = (f & 3) << 2;
            int grow = row0 + ar;
            if (grow >= Nn) grow = Nn - 1;
            float4 val = *(const float4*)(v + (size_t)grow * 128 + kt + kl);
            float* q = &Ad[ar * 36 + 2 * kl];
            *(float4*)(q)     = make_float4(val.x, val.x, val.y, val.y);
            *(float4*)(q + 4) = make_float4(val.z, val.z, val.w, val.w);
        }
        fill_Bs(Bs, w0, kt, t);
        __syncthreads();
        mma16(Ad, Bs, r0, c0, acc);
    }
    // K = 128 extra dim: rel_feat scalar * w0 row 128
    {
        ull wx[4];
#pragma unroll
        for (int j = 0; j < 4; j++) wx[j] = *(const ull*)&w0[128 * 128 + c0 + 2 * j];
#pragma unroll
        for (int i = 0; i < 8; i++) {
            ull rl2 = dupf(s_rel[r0 + i]);
#pragma unroll
            for (int j = 0; j < 4; j++) ffma2(acc[i][j], rl2, wx[j]);
        }
    }
    selu_store(Hs, acc, r0, c0);
    acc_init(acc, b1, c0);
    hidden_layer(w1, Hs, Ad, Bs, t, r0, c0, acc);
    selu_store(Hs, acc, r0, c0);
    acc_init(acc, b2, c0);
    hidden_layer(w2, Hs, Ad, Bs, t, r0, c0, acc);

#pragma unroll
    for (int i = 0; i < 8; i++) {
        int row = row0 + r0 + i;
        if (row < Nn) {
            int cl = s_cl[r0 + i];
            float* crow = vc + (size_t)cl * 128 + c0;
            float2 p0 = unpk(acc[i][0]), p1 = unpk(acc[i][1]);
            float2 p2 = unpk(acc[i][2]), p3 = unpk(acc[i][3]);
            float rr[8] = {p0.x, p0.y, p1.x, p1.y, p2.x, p2.y, p3.x, p3.y};
#pragma unroll
            for (int j = 0; j < 8; j++) atomicAdd(&crow[j], rr[j]);
        }
    }
}

// ---------------- coarse edge encoder ----------------
__global__ void __launch_bounds__(128) eenc_kernel(
    const int* __restrict__ cei, const float* __restrict__ cpos,
    const float* __restrict__ w0, const float* __restrict__ b0,
    const float* __restrict__ w1, const float* __restrict__ b1,
    const float* __restrict__ w2, const float* __restrict__ b2,
    float* __restrict__ ec) {
    extern __shared__ float sm[];
    float* Ad = sm + AD_OFF;
    float* Bs = sm + BS_OFF;
    float* Hs = sm + HS_OFF;
    float* s_crel = sm + IX_OFF;

    const int t = threadIdx.x;
    const int row0 = blockIdx.x * 64;
    if (t < 64) {
        int r = row0 + t;
        if (r >= ECc) r = ECc - 1;
        int a = cei[r];
        int b = cei[ECc + r];
        float dx = cpos[2 * a] - cpos[2 * b];
        float dy = cpos[2 * a + 1] - cpos[2 * b + 1];
        s_crel[t] = sqrtf(dx * dx + dy * dy + 1e-12f);
    }
    const int c0 = (t & 15) * 8;
    const int r0 = (t >> 4) * 8;
    __syncthreads();

    // layer 0 (K = 1)
#pragma unroll
    for (int i = 0; i < 8; i++) {
        float cr = s_crel[r0 + i];
#pragma unroll
        for (int j = 0; j < 8; j++)
            Hs[(r0 + i) * 132 + c0 + j] =
                selu_f(fmaf(cr, __ldg(&w0[c0 + j]), __ldg(&b0[c0 + j])));
    }

    ull acc[8][4];
    acc_init(acc, b1, c0);
    hidden_layer(w1, Hs, Ad, Bs, t, r0, c0, acc);
    selu_store(Hs, acc, r0, c0);
    acc_init(acc, b2, c0);
    hidden_layer(w2, Hs, Ad, Bs, t, r0, c0, acc);

#pragma unroll
    for (int i = 0; i < 8; i++) {
        int row = row0 + r0 + i;
        if (row < ECc) {
            float* erow = ec + (size_t)row * 128 + c0;
            float2 p0 = unpk(acc[i][0]), p1 = unpk(acc[i][1]);
            float2 p2 = unpk(acc[i][2]), p3 = unpk(acc[i][3]);
            *(float4*)erow       = make_float4(p0.x, p0.y, p1.x, p1.y);
            *(float4*)(erow + 4) = make_float4(p2.x, p2.y, p3.x, p3.y);
        }
    }
}

// ---------------- small helpers ----------------
__global__ void deg_scatter(const int* __restrict__ dst, float* __restrict__ deg) {
    int i = blockIdx.x * blockDim.x + threadIdx.x;
    if (i < Ee) atomicAdd(&deg[dst[i]], 1.f);
}
__global__ void cpos_scatter(const float* __restrict__ pos, const int* __restrict__ cluster,
                             float* __restrict__ cposs, float* __restrict__ ccnt) {
    int i = blockIdx.x * blockDim.x + threadIdx.x;
    if (i < Nn) {
        int c = cluster[i];
        atomicAdd(&cposs[2 * c], pos[2 * i]);
        atomicAdd(&cposs[2 * c + 1], pos[2 * i + 1]);
        atomicAdd(&ccnt[c], 1.f);
    }
}
__global__ void cpos_fin(const float* __restrict__ cposs, const float* __restrict__ ccnt,
                         float* __restrict__ cpos, float* __restrict__ cinv) {
    int c = blockIdx.x * blockDim.x + threadIdx.x;
    if (c < NCc) {
        float inv = 1.f / fmaxf(ccnt[c], 1.f);
        cpos[2 * c] = cposs[2 * c] * inv;
        cpos[2 * c + 1] = cposs[2 * c + 1] * inv;
        cinv[c] = inv;
    }
}
__global__ void vc_scale(float* __restrict__ vc, const float* __restrict__ cinv) {
    int i = blockIdx.x * blockDim.x + threadIdx.x;
    if (i < NCc * 128) vc[i] *= cinv[i >> 7];
}

// ---------------- launch ----------------
extern "C" void kernel_launch(void* const* d_in, const int* in_sizes, int n_in,
                              void* d_out, int out_size) {
    const float* v0      = (const float*)d_in[0];
    const float* e0      = (const float*)d_in[1];
    const float* pos     = (const float*)d_in[2];
    const int*   ei      = (const int*)d_in[3];
    const int*   cluster = (const int*)d_in[4];
    const int*   cei     = (const int*)d_in[5];
    const float* ew0 = (const float*)d_in[6],  *eb0 = (const float*)d_in[7];
    const float* ew1 = (const float*)d_in[8],  *eb1 = (const float*)d_in[9];
    const float* ew2 = (const float*)d_in[10], *eb2 = (const float*)d_in[11];
    const float* nw0 = (const float*)d_in[12], *nb0 = (const float*)d_in[13];
    const float* nw1 = (const float*)d_in[14], *nb1 = (const float*)d_in[15];
    const float* nw2 = (const float*)d_in[16], *nb2 = (const float*)d_in[17];
    const float* pw0 = (const float*)d_in[18], *pb0 = (const float*)d_in[19];
    const float* pw1 = (const float*)d_in[20], *pb1 = (const float*)d_in[21];
    const float* pw2 = (const float*)d_in[22], *pb2 = (const float*)d_in[23];
    const float* qw0 = (const float*)d_in[24], *qb0 = (const float*)d_in[25];
    const float* qw1 = (const float*)d_in[26], *qb1 = (const float*)d_in[27];
    const float* qw2 = (const float*)d_in[28], *qb2 = (const float*)d_in[29];

    float* out    = (float*)d_out;
    float* out_vc = out;
    float* out_ec = out + OFF_EC;
    float* vbuf   = out + OFF_V;
    float* ebuf   = out + OFF_E;

    float *agg, *deg, *cposs, *ccnt, *cpos, *cinv;
    cudaGetSymbolAddress((void**)&agg,   g_agg);
    cudaGetSymbolAddress((void**)&deg,   g_deg);
    cudaGetSymbolAddress((void**)&cposs, g_cposs);
    cudaGetSymbolAddress((void**)&ccnt,  g_ccnt);
    cudaGetSymbolAddress((void**)&cpos,  g_cpos);
    cudaGetSymbolAddress((void**)&cinv,  g_cinv);

    cudaFuncSetAttribute(edge_kernel, cudaFuncAttributeMaxDynamicSharedMemorySize, SMEM_BYTES);
    cudaFuncSetAttribute(node_kernel, cudaFuncAttributeMaxDynamicSharedMemorySize, SMEM_BYTES);
    cudaFuncSetAttribute(pool_kernel, cudaFuncAttributeMaxDynamicSharedMemorySize, SMEM_BYTES);
    cudaFuncSetAttribute(eenc_kernel, cudaFuncAttributeMaxDynamicSharedMemorySize, SMEM_BYTES);

    cudaMemcpyAsync(vbuf, v0, sizeof(float) * (size_t)Nn * 128, cudaMemcpyDeviceToDevice, 0);
    cudaMemcpyAsync(ebuf, e0, sizeof(float) * (size_t)Ee * 128, cudaMemcpyDeviceToDevice, 0);

    const int* src  = ei;
    const int* dstp = ei + Ee;

    cudaMemsetAsync(deg, 0, sizeof(float) * Nn, 0);
    deg_scatter<<<(Ee + 255) / 256, 256>>>(dstp, deg);

    for (int d = 0; d < 4; d++) {
        cudaMemsetAsync(agg, 0, sizeof(float) * (size_t)Nn * 128, 0);
        edge_kernel<<<(Ee + 63) / 64, 128, SMEM_BYTES>>>(
            ebuf, vbuf, src, dstp,
            ew0 + (size_t)d * 384 * 128, eb0 + d * 128,
            ew1 + (size_t)d * 128 * 128, eb1 + d * 128,
            ew2 + (size_t)d * 128 * 128, eb2 + d * 128, agg);
        node_kernel<<<(Nn + 63) / 64, 128, SMEM_BYTES>>>(
            vbuf, agg, deg,
            nw0 + (size_t)d * 256 * 128, nb0 + d * 128,
            nw1 + (size_t)d * 128 * 128, nb1 + d * 128,
            nw2 + (size_t)d * 128 * 128, nb2 + d * 128);
    }

    cudaMemsetAsync(cposs, 0, sizeof(float) * NCc * 2, 0);
    cudaMemsetAsync(ccnt, 0, sizeof(float) * NCc, 0);
    cpos_scatter<<<(Nn + 255) / 256, 256>>>(pos, cluster, cposs, ccnt);
    cpos_fin<<<(NCc + 255) / 256, 256>>>(cposs, ccnt, cpos, cinv);

    cudaMemsetAsync(out_vc, 0, sizeof(float) * NCc * 128, 0);
    pool_kernel<<<(Nn + 63) / 64, 128, SMEM_BYTES>>>(vbuf, pos, cluster, cpos,
                                                     pw0, pb0, pw1, pb1, pw2, pb2, out_vc);
    vc_scale<<<(NCc * 128 + 255) / 256, 256>>>(out_vc, cinv);

    eenc_kernel<<<(ECc + 63) / 64, 128, SMEM_BYTES>>>(cei, cpos, qw0, qb0, qw1, qb1, qw2, qb2, out_ec);
}

// round 5
// speedup vs baseline: 1.2519x; 1.0969x over previous
#include <cuda_runtime.h>
#include <math.h>

#define Nn  50000
#define Ee  300000
#define NCc 12500
#define ECc 75000

#define OFF_EC 1600000
#define OFF_V  11200000
#define OFF_E  17600000

typedef unsigned long long ull;

// smem layout (floats):
//   As[2 * 64*20]  = 2560   (layer-0 streamed A tiles, double buffered)
//   Bs[2 * 16*192] = 6144   (weight tiles, group-stride-12 swizzle, double buffered)
//   Hs[64 * 132]   = 8448   (activations)
//   idx            = 160
#define AS_OFF 0
#define AS_BUF 1280
#define BS_OFF 2560
#define BS_BUF 3072
#define HS_OFF 8704
#define IX_OFF 17152
#define SMEM_BYTES ((17152 + 160) * 4)

// ---------------- device scratch ----------------
__device__ float g_agg[Nn * 128];
__device__ float g_deg[Nn];
__device__ float g_cposs[NCc * 2];
__device__ float g_ccnt[NCc];
__device__ float g_cpos[NCc * 2];
__device__ float g_cinv[NCc];

__device__ __forceinline__ float selu_f(float x) {
    return x > 0.f ? 1.0507009873554805f * x : 1.7580993408473766f * expm1f(x);
}
__device__ __forceinline__ void ffma2(ull& d, ull a, ull b) {
    asm("fma.rn.f32x2 %0, %1, %2, %0;" : "+l"(d) : "l"(a), "l"(b));
}
__device__ __forceinline__ float2 unpk(ull p) {
    float2 f;
    asm("mov.b64 {%0, %1}, %2;" : "=f"(f.x), "=f"(f.y) : "l"(p));
    return f;
}
__device__ __forceinline__ ull dupf(float x) {
    ull r;
    asm("mov.b64 %0, {%1, %1};" : "=l"(r) : "f"(x));
    return r;
}

__device__ __forceinline__ void acc_init(ull (&acc)[8][4], const float* __restrict__ b, int c0) {
    ull bb[4];
#pragma unroll
    for (int j = 0; j < 4; j++) bb[j] = *(const ull*)&b[c0 + 2 * j];
#pragma unroll
    for (int i = 0; i < 8; i++)
#pragma unroll
        for (int j = 0; j < 4; j++) acc[i][j] = bb[j];
}

// Bs layout: Bs[k*192 + g*12 + (c%8)], g = c/8.  g*12 mod 32 covers all banks
// disjointly per quarter-warp for both LDS.128 offsets (+0 and +4).
__device__ __forceinline__ void fill_Bs(float* Bs, const float* __restrict__ W, int kt, int t) {
    const float4* wsrc = (const float4*)(W + (size_t)kt * 128);
#pragma unroll
    for (int i = 0; i < 4; i++) {
        int fi = i * 128 + t;      // float4 index within 16x128 tile
        float4 w = wsrc[fi];
        int k = fi >> 5;
        int q = fi & 31;
        *(float4*)&Bs[k * 192 + (q >> 1) * 12 + (q & 1) * 4] = w;
    }
}

// acc[8 rows][4 col-pairs] += A(64 x STRIDE)[:, koff:koff+16] @ Bs-tile
template <int STRIDE>
__device__ __forceinline__ void mma16(const float* A, int koff, const float* Bs,
                                      int r0, int gb, ull (&acc)[8][4]) {
#pragma unroll
    for (int k4 = 0; k4 < 4; k4++) {
        float4 a4[8];
#pragma unroll
        for (int i = 0; i < 8; i++)
            a4[i] = *(const float4*)&A[(r0 + i) * STRIDE + koff + 4 * k4];
#pragma unroll
        for (int kk = 0; kk < 4; kk++) {
            const float* bp = &Bs[(4 * k4 + kk) * 192 + gb];
            ulonglong2 bA = *(const ulonglong2*)bp;
            ulonglong2 bB = *(const ulonglong2*)(bp + 4);
#pragma unroll
            for (int i = 0; i < 8; i++) {
                float av = (kk == 0) ? a4[i].x : (kk == 1) ? a4[i].y
                         : (kk == 2) ? a4[i].z : a4[i].w;
                ull ad = dupf(av);
                ffma2(acc[i][0], ad, bA.x);
                ffma2(acc[i][1], ad, bA.y);
                ffma2(acc[i][2], ad, bB.x);
                ffma2(acc[i][3], ad, bB.y);
            }
        }
    }
}

__device__ __forceinline__ void selu_store(float* Hs, ull (&acc)[8][4], int r0, int c0) {
#pragma unroll
    for (int i = 0; i < 8; i++) {
        float2 p0 = unpk(acc[i][0]), p1 = unpk(acc[i][1]);
        float2 p2 = unpk(acc[i][2]), p3 = unpk(acc[i][3]);
        *(float4*)&Hs[(r0 + i) * 132 + c0] =
            make_float4(selu_f(p0.x), selu_f(p0.y), selu_f(p1.x), selu_f(p1.y));
        *(float4*)&Hs[(r0 + i) * 132 + c0 + 4] =
            make_float4(selu_f(p2.x), selu_f(p2.y), selu_f(p3.x), selu_f(p3.y));
    }
}

// hidden 128->128 layer, Bs double buffered, ONE sync per K-tile
__device__ __forceinline__ void hidden_layer(const float* __restrict__ W,
                                             const float* Hs, float* BsBase,
                                             int t, int r0, int gb, ull (&acc)[8][4]) {
    fill_Bs(BsBase, W, 0, t);
    __syncthreads();
#pragma unroll 1
    for (int kt = 0; kt < 8; kt++) {
        if (kt < 7) fill_Bs(BsBase + ((kt + 1) & 1) * BS_BUF, W, (kt + 1) * 16, t);
        mma16<132>(Hs, kt * 16, BsBase + (kt & 1) * BS_BUF, r0, gb, acc);
        __syncthreads();
    }
}

// ---------------- edge: e += MLP([e, v[src], v[dst]]); agg[dst] += e ----------------
__global__ void __launch_bounds__(128) edge_kernel(
    float* __restrict__ e, const float* __restrict__ v,
    const int* __restrict__ src, const int* __restrict__ dst,
    const float* __restrict__ w0, const float* __restrict__ b0,
    const float* __restrict__ w1, const float* __restrict__ b1,
    const float* __restrict__ w2, const float* __restrict__ b2,
    float* __restrict__ agg) {
    extern __shared__ float sm[];
    float* As = sm + AS_OFF;
    float* Bs = sm + BS_OFF;
    float* Hs = sm + HS_OFF;
    int* s_src = (int*)(sm + IX_OFF);
    int* s_dst = s_src + 64;

    const int t = threadIdx.x;
    const int row0 = blockIdx.x * 64;
    if (t < 64) {
        int r = row0 + t;
        if (r >= Ee) r = Ee - 1;
        s_src[t] = src[r];
        s_dst[t] = dst[r];
    }
    const int c0 = (t & 15) * 8;
    const int gb = (t & 15) * 12;
    const int r0 = (t >> 4) * 8;
    __syncthreads();

    ull acc[8][4];
    acc_init(acc, b0, c0);

    // layer 0: K = 384 streamed (gathered A + W tiles, double buffered)
    auto fill_As = [&](float* dstA, int kt) {
#pragma unroll
        for (int i = 0; i < 2; i++) {
            int f = t * 2 + i;
            int ar = f >> 2;
            int kl = (f & 3) << 2;
            int k = kt + kl;
            int grow = row0 + ar;
            if (grow >= Ee) grow = Ee - 1;
            float4 val;
            if (k < 128)      val = *(const float4*)(e + (size_t)grow * 128 + k);
            else if (k < 256) val = *(const float4*)(v + (size_t)s_src[ar] * 128 + (k - 128));
            else              val = *(const float4*)(v + (size_t)s_dst[ar] * 128 + (k - 256));
            *(float4*)&dstA[ar * 20 + kl] = val;
        }
    };
    fill_As(As, 0);
    fill_Bs(Bs, w0, 0, t);
    __syncthreads();
#pragma unroll 1
    for (int kt = 0; kt < 24; kt++) {
        if (kt < 23) {
            int nb = (kt + 1) & 1;
            fill_As(As + nb * AS_BUF, (kt + 1) * 16);
            fill_Bs(Bs + nb * BS_BUF, w0, (kt + 1) * 16, t);
        }
        mma16<20>(As + (kt & 1) * AS_BUF, 0, Bs + (kt & 1) * BS_BUF, r0, gb, acc);
        __syncthreads();
    }
    selu_store(Hs, acc, r0, c0);
    acc_init(acc, b1, c0);
    hidden_layer(w1, Hs, Bs, t, r0, gb, acc);
    selu_store(Hs, acc, r0, c0);
    acc_init(acc, b2, c0);
    hidden_layer(w2, Hs, Bs, t, r0, gb, acc);

#pragma unroll
    for (int i = 0; i < 8; i++) {
        int row = row0 + r0 + i;
        if (row < Ee) {
            int dn = s_dst[r0 + i];
            float* erow = e + (size_t)row * 128 + c0;
            float* arow = agg + (size_t)dn * 128 + c0;
            float2 p0 = unpk(acc[i][0]), p1 = unpk(acc[i][1]);
            float2 p2 = unpk(acc[i][2]), p3 = unpk(acc[i][3]);
            float4 e0 = *(float4*)erow;
            float4 e1 = *(float4*)(erow + 4);
            float rr[8] = {e0.x + p0.x, e0.y + p0.y, e0.z + p1.x, e0.w + p1.y,
                           e1.x + p2.x, e1.y + p2.y, e1.z + p3.x, e1.w + p3.y};
            *(float4*)erow       = make_float4(rr[0], rr[1], rr[2], rr[3]);
            *(float4*)(erow + 4) = make_float4(rr[4], rr[5], rr[6], rr[7]);
#pragma unroll
            for (int j = 0; j < 8; j++) atomicAdd(&arow[j], rr[j]);
        }
    }
}

// ---------------- node: v += MLP([v, agg/deg]) ----------------
__global__ void __launch_bounds__(128) node_kernel(
    float* __restrict__ v, const float* __restrict__ agg, const float* __restrict__ deg,
    const float* __restrict__ w0, const float* __restrict__ b0,
    const float* __restrict__ w1, const float* __restrict__ b1,
    const float* __restrict__ w2, const float* __restrict__ b2) {
    extern __shared__ float sm[];
    float* As = sm + AS_OFF;
    float* Bs = sm + BS_OFF;
    float* Hs = sm + HS_OFF;
    float* s_inv = sm + IX_OFF;

    const int t = threadIdx.x;
    const int row0 = blockIdx.x * 64;
    if (t < 64) {
        int r = row0 + t;
        if (r >= Nn) r = Nn - 1;
        s_inv[t] = 1.f / fmaxf(deg[r], 1.f);
    }
    const int c0 = (t & 15) * 8;
    const int gb = (t & 15) * 12;
    const int r0 = (t >> 4) * 8;
    __syncthreads();

    ull acc[8][4];
    acc_init(acc, b0, c0);

    auto fill_As = [&](float* dstA, int kt) {
#pragma unroll
        for (int i = 0; i < 2; i++) {
            int f = t * 2 + i;
            int ar = f >> 2;
            int kl = (f & 3) << 2;
            int k = kt + kl;
            int grow = row0 + ar;
            if (grow >= Nn) grow = Nn - 1;
            float4 val;
            if (k < 128) {
                val = *(const float4*)(v + (size_t)grow * 128 + k);
            } else {
                val = *(const float4*)(agg + (size_t)grow * 128 + (k - 128));
                float sc = s_inv[ar];
                val.x *= sc; val.y *= sc; val.z *= sc; val.w *= sc;
            }
            *(float4*)&dstA[ar * 20 + kl] = val;
        }
    };
    fill_As(As, 0);
    fill_Bs(Bs, w0, 0, t);
    __syncthreads();
#pragma unroll 1
    for (int kt = 0; kt < 16; kt++) {
        if (kt < 15) {
            int nb = (kt + 1) & 1;
            fill_As(As + nb * AS_BUF, (kt + 1) * 16);
            fill_Bs(Bs + nb * BS_BUF, w0, (kt + 1) * 16, t);
        }
        mma16<20>(As + (kt & 1) * AS_BUF, 0, Bs + (kt & 1) * BS_BUF, r0, gb, acc);
        __syncthreads();
    }
    selu_store(Hs, acc, r0, c0);
    acc_init(acc, b1, c0);
    hidden_layer(w1, Hs, Bs, t, r0, gb, acc);
    selu_store(Hs, acc, r0, c0);
    acc_init(acc, b2, c0);
    hidden_layer(w2, Hs, Bs, t, r0, gb, acc);

#pragma unroll
    for (int i = 0; i < 8; i++) {
        int row = row0 + r0 + i;
        if (row < Nn) {
            float* vrow = v + (size_t)row * 128 + c0;
            float2 p0 = unpk(acc[i][0]), p1 = unpk(acc[i][1]);
            float2 p2 = unpk(acc[i][2]), p3 = unpk(acc[i][3]);
            float4 v0 = *(float4*)vrow;
            float4 v1 = *(float4*)(vrow + 4);
            *(float4*)vrow       = make_float4(v0.x + p0.x, v0.y + p0.y, v0.z + p1.x, v0.w + p1.y);
            *(float4*)(vrow + 4) = make_float4(v1.x + p2.x, v1.y + p2.y, v1.z + p3.x, v1.w + p3.y);
        }
    }
}

// ---------------- pool: atomic-add MLP([v, rel]) into vc sums ----------------
__global__ void __launch_bounds__(128) pool_kernel(
    const float* __restrict__ v, const float* __restrict__ pos,
    const int* __restrict__ cluster, const float* __restrict__ cpos,
    const float* __restrict__ w0, const float* __restrict__ b0,
    const float* __restrict__ w1, const float* __restrict__ b1,
    const float* __restrict__ w2, const float* __restrict__ b2,
    float* __restrict__ vc) {
    extern __shared__ float sm[];
    float* As = sm + AS_OFF;
    float* Bs = sm + BS_OFF;
    float* Hs = sm + HS_OFF;
    float* s_rel = sm + IX_OFF;
    int* s_cl = (int*)(sm + IX_OFF + 64);

    const int t = threadIdx.x;
    const int row0 = blockIdx.x * 64;
    if (t < 64) {
        int r = row0 + t;
        if (r >= Nn) r = Nn - 1;
        int cl = cluster[r];
        float dx = pos[2 * r] - cpos[2 * cl];
        float dy = pos[2 * r + 1] - cpos[2 * cl + 1];
        s_rel[t] = sqrtf(dx * dx + dy * dy + 1e-12f);
        s_cl[t] = cl;
    }
    const int c0 = (t & 15) * 8;
    const int gb = (t & 15) * 12;
    const int r0 = (t >> 4) * 8;
    __syncthreads();

    ull acc[8][4];
    acc_init(acc, b0, c0);

    auto fill_As = [&](float* dstA, int kt) {
#pragma unroll
        for (int i = 0; i < 2; i++) {
            int f = t * 2 + i;
            int ar = f >> 2;
            int kl = (f & 3) << 2;
            int grow = row0 + ar;
            if (grow >= Nn) grow = Nn - 1;
            float4 val = *(const float4*)(v + (size_t)grow * 128 + kt + kl);
            *(float4*)&dstA[ar * 20 + kl] = val;
        }
    };
    fill_As(As, 0);
    fill_Bs(Bs, w0, 0, t);
    __syncthreads();
#pragma unroll 1
    for (int kt = 0; kt < 8; kt++) {
        if (kt < 7) {
            int nb = (kt + 1) & 1;
            fill_As(As + nb * AS_BUF, (kt + 1) * 16);
            fill_Bs(Bs + nb * BS_BUF, w0, (kt + 1) * 16, t);
        }
        mma16<20>(As + (kt & 1) * AS_BUF, 0, Bs + (kt & 1) * BS_BUF, r0, gb, acc);
        __syncthreads();
    }
    // extra K dim 128: rel_feat scalar
    {
        ull wx[4];
#pragma unroll
        for (int j = 0; j < 4; j++) wx[j] = *(const ull*)&w0[128 * 128 + c0 + 2 * j];
#pragma unroll
        for (int i = 0; i < 8; i++) {
            ull rl2 = dupf(s_rel[r0 + i]);
#pragma unroll
            for (int j = 0; j < 4; j++) ffma2(acc[i][j], rl2, wx[j]);
        }
    }
    selu_store(Hs, acc, r0, c0);
    acc_init(acc, b1, c0);
    hidden_layer(w1, Hs, Bs, t, r0, gb, acc);
    selu_store(Hs, acc, r0, c0);
    acc_init(acc, b2, c0);
    hidden_layer(w2, Hs, Bs, t, r0, gb, acc);

#pragma unroll
    for (int i = 0; i < 8; i++) {
        int row = row0 + r0 + i;
        if (row < Nn) {
            int cl = s_cl[r0 + i];
            float* crow = vc + (size_t)cl * 128 + c0;
            float2 p0 = unpk(acc[i][0]), p1 = unpk(acc[i][1]);
            float2 p2 = unpk(acc[i][2]), p3 = unpk(acc[i][3]);
            float rr[8] = {p0.x, p0.y, p1.x, p1.y, p2.x, p2.y, p3.x, p3.y};
#pragma unroll
            for (int j = 0; j < 8; j++) atomicAdd(&crow[j], rr[j]);
        }
    }
}

// ---------------- coarse edge encoder ----------------
__global__ void __launch_bounds__(128) eenc_kernel(
    const int* __restrict__ cei, const float* __restrict__ cpos,
    const float* __restrict__ w0, const float* __restrict__ b0,
    const float* __restrict__ w1, const float* __restrict__ b1,
    const float* __restrict__ w2, const float* __restrict__ b2,
    float* __restrict__ ec) {
    extern __shared__ float sm[];
    float* Bs = sm + BS_OFF;
    float* Hs = sm + HS_OFF;
    float* s_crel = sm + IX_OFF;

    const int t = threadIdx.x;
    const int row0 = blockIdx.x * 64;
    if (t < 64) {
        int r = row0 + t;
        if (r >= ECc) r = ECc - 1;
        int a = cei[r];
        int b = cei[ECc + r];
        float dx = cpos[2 * a] - cpos[2 * b];
        float dy = cpos[2 * a + 1] - cpos[2 * b + 1];
        s_crel[t] = sqrtf(dx * dx + dy * dy + 1e-12f);
    }
    const int c0 = (t & 15) * 8;
    const int gb = (t & 15) * 12;
    const int r0 = (t >> 4) * 8;
    __syncthreads();

    // layer 0 (K = 1)
#pragma unroll
    for (int i = 0; i < 8; i++) {
        float cr = s_crel[r0 + i];
#pragma unroll
        for (int j = 0; j < 8; j++)
            Hs[(r0 + i) * 132 + c0 + j] =
                selu_f(fmaf(cr, __ldg(&w0[c0 + j]), __ldg(&b0[c0 + j])));
    }

    ull acc[8][4];
    acc_init(acc, b1, c0);
    hidden_layer(w1, Hs, Bs, t, r0, gb, acc);
    selu_store(Hs, acc, r0, c0);
    acc_init(acc, b2, c0);
    hidden_layer(w2, Hs, Bs, t, r0, gb, acc);

#pragma unroll
    for (int i = 0; i < 8; i++) {
        int row = row0 + r0 + i;
        if (row < ECc) {
            float* erow = ec + (size_t)row * 128 + c0;
            float2 p0 = unpk(acc[i][0]), p1 = unpk(acc[i][1]);
            float2 p2 = unpk(acc[i][2]), p3 = unpk(acc[i][3]);
            *(float4*)erow       = make_float4(p0.x, p0.y, p1.x, p1.y);
            *(float4*)(erow + 4) = make_float4(p2.x, p2.y, p3.x, p3.y);
        }
    }
}

// ---------------- small helpers ----------------
__global__ void deg_scatter(const int* __restrict__ dst, float* __restrict__ deg) {
    int i = blockIdx.x * blockDim.x + threadIdx.x;
    if (i < Ee) atomicAdd(&deg[dst[i]], 1.f);
}
__global__ void cpos_scatter(const float* __restrict__ pos, const int* __restrict__ cluster,
                             float* __restrict__ cposs, float* __restrict__ ccnt) {
    int i = blockIdx.x * blockDim.x + threadIdx.x;
    if (i < Nn) {
        int c = cluster[i];
        atomicAdd(&cposs[2 * c], pos[2 * i]);
        atomicAdd(&cposs[2 * c + 1], pos[2 * i + 1]);
        atomicAdd(&ccnt[c], 1.f);
    }
}
__global__ void cpos_fin(const float* __restrict__ cposs, const float* __restrict__ ccnt,
                         float* __restrict__ cpos, float* __restrict__ cinv) {
    int c = blockIdx.x * blockDim.x + threadIdx.x;
    if (c < NCc) {
        float inv = 1.f / fmaxf(ccnt[c], 1.f);
        cpos[2 * c] = cposs[2 * c] * inv;
        cpos[2 * c + 1] = cposs[2 * c + 1] * inv;
        cinv[c] = inv;
    }
}
__global__ void vc_scale(float* __restrict__ vc, const float* __restrict__ cinv) {
    int i = blockIdx.x * blockDim.x + threadIdx.x;
    if (i < NCc * 128) vc[i] *= cinv[i >> 7];
}

// ---------------- launch ----------------
extern "C" void kernel_launch(void* const* d_in, const int* in_sizes, int n_in,
                              void* d_out, int out_size) {
    const float* v0      = (const float*)d_in[0];
    const float* e0      = (const float*)d_in[1];
    const float* pos     = (const float*)d_in[2];
    const int*   ei      = (const int*)d_in[3];
    const int*   cluster = (const int*)d_in[4];
    const int*   cei     = (const int*)d_in[5];
    const float* ew0 = (const float*)d_in[6],  *eb0 = (const float*)d_in[7];
    const float* ew1 = (const float*)d_in[8],  *eb1 = (const float*)d_in[9];
    const float* ew2 = (const float*)d_in[10], *eb2 = (const float*)d_in[11];
    const float* nw0 = (const float*)d_in[12], *nb0 = (const float*)d_in[13];
    const float* nw1 = (const float*)d_in[14], *nb1 = (const float*)d_in[15];
    const float* nw2 = (const float*)d_in[16], *nb2 = (const float*)d_in[17];
    const float* pw0 = (const float*)d_in[18], *pb0 = (const float*)d_in[19];
    const float* pw1 = (const float*)d_in[20], *pb1 = (const float*)d_in[21];
    const float* pw2 = (const float*)d_in[22], *pb2 = (const float*)d_in[23];
    const float* qw0 = (const float*)d_in[24], *qb0 = (const float*)d_in[25];
    const float* qw1 = (const float*)d_in[26], *qb1 = (const float*)d_in[27];
    const float* qw2 = (const float*)d_in[28], *qb2 = (const float*)d_in[29];

    float* out    = (float*)d_out;
    float* out_vc = out;
    float* out_ec = out + OFF_EC;
    float* vbuf   = out + OFF_V;
    float* ebuf   = out + OFF_E;

    float *agg, *deg, *cposs, *ccnt, *cpos, *cinv;
    cudaGetSymbolAddress((void**)&agg,   g_agg);
    cudaGetSymbolAddress((void**)&deg,   g_deg);
    cudaGetSymbolAddress((void**)&cposs, g_cposs);
    cudaGetSymbolAddress((void**)&ccnt,  g_ccnt);
    cudaGetSymbolAddress((void**)&cpos,  g_cpos);
    cudaGetSymbolAddress((void**)&cinv,  g_cinv);

    cudaFuncSetAttribute(edge_kernel, cudaFuncAttributeMaxDynamicSharedMemorySize, SMEM_BYTES);
    cudaFuncSetAttribute(node_kernel, cudaFuncAttributeMaxDynamicSharedMemorySize, SMEM_BYTES);
    cudaFuncSetAttribute(pool_kernel, cudaFuncAttributeMaxDynamicSharedMemorySize, SMEM_BYTES);
    cudaFuncSetAttribute(eenc_kernel, cudaFuncAttributeMaxDynamicSharedMemorySize, SMEM_BYTES);

    cudaMemcpyAsync(vbuf, v0, sizeof(float) * (size_t)Nn * 128, cudaMemcpyDeviceToDevice, 0);
    cudaMemcpyAsync(ebuf, e0, sizeof(float) * (size_t)Ee * 128, cudaMemcpyDeviceToDevice, 0);

    const int* src  = ei;
    const int* dstp = ei + Ee;

    cudaMemsetAsync(deg, 0, sizeof(float) * Nn, 0);
    deg_scatter<<<(Ee + 255) / 256, 256>>>(dstp, deg);

    for (int d = 0; d < 4; d++) {
        cudaMemsetAsync(agg, 0, sizeof(float) * (size_t)Nn * 128, 0);
        edge_kernel<<<(Ee + 63) / 64, 128, SMEM_BYTES>>>(
            ebuf, vbuf, src, dstp,
            ew0 + (size_t)d * 384 * 128, eb0 + d * 128,
            ew1 + (size_t)d * 128 * 128, eb1 + d * 128,
            ew2 + (size_t)d * 128 * 128, eb2 + d * 128, agg);
        node_kernel<<<(Nn + 63) / 64, 128, SMEM_BYTES>>>(
            vbuf, agg, deg,
            nw0 + (size_t)d * 256 * 128, nb0 + d * 128,
            nw1 + (size_t)d * 128 * 128, nb1 + d * 128,
            nw2 + (size_t)d * 128 * 128, nb2 + d * 128);
    }

    cudaMemsetAsync(cposs, 0, sizeof(float) * NCc * 2, 0);
    cudaMemsetAsync(ccnt, 0, sizeof(float) * NCc, 0);
    cpos_scatter<<<(Nn + 255) / 256, 256>>>(pos, cluster, cposs, ccnt);
    cpos_fin<<<(NCc + 255) / 256, 256>>>(cposs, ccnt, cpos, cinv);

    cudaMemsetAsync(out_vc, 0, sizeof(float) * NCc * 128, 0);
    pool_kernel<<<(Nn + 63) / 64, 128, SMEM_BYTES>>>(vbuf, pos, cluster, cpos,
                                                     pw0, pb0, pw1, pb1, pw2, pb2, out_vc);
    vc_scale<<<(NCc * 128 + 255) / 256, 256>>>(out_vc, cinv);

    eenc_kernel<<<(ECc + 63) / 64, 128, SMEM_BYTES>>>(cei, cpos, qw0, qb0, qw1, qb1, qw2, qb2, out_ec);
}